// round 1
// baseline (speedup 1.0000x reference)
#include <cuda_runtime.h>

// KnnLoss: B=4, N=8192, C=3, K=16, RADIUS=0.5, L2 norm.
// loss = mean over (b, i, k) of ||flow_i - flow_nbr||, where nbr is the k-th
// nearest point of i, replaced by self (=> zero contribution) if dist > RADIUS.
// Equivalent: sum over the min(16, m) nearest within-radius neighbors.

#define BB 4
#define NN 8192
#define KK 16
#define TPB 256

__device__ float g_partials[(NN / TPB) * BB];

__global__ __launch_bounds__(TPB, 1) void knn_loss_kernel(
    const float* __restrict__ pc, const float* __restrict__ flow) {
    extern __shared__ float4 spts[];  // NN float4: (x, y, z, |p|^2) = 128 KB

    const int b = blockIdx.y;
    const float* pcb = pc + (size_t)b * NN * 3;
    const float* flb = flow + (size_t)b * NN * 3;

    // Stage the whole batch's point cloud (+ precomputed squared norms) in SMEM.
    for (int n = threadIdx.x; n < NN; n += TPB) {
        float x = pcb[3 * n + 0];
        float y = pcb[3 * n + 1];
        float z = pcb[3 * n + 2];
        spts[n] = make_float4(x, y, z, x * x + y * y + z * z);
    }
    __syncthreads();

    const int qi = blockIdx.x * TPB + threadIdx.x;
    const float4 q = spts[qi];
    const float qx = q.x, qy = q.y, qz = q.z, qsq = q.w;

    // Radius-gated top-K: sorted ascending by clamped d^2.
    // Empty slots keep idx = qi so they contribute exactly 0 in the epilogue.
    float dk[KK];
    int ik[KK];
#pragma unroll
    for (int s = 0; s < KK; ++s) {
        dk[s] = 3.0e38f;
        ik[s] = qi;
    }

    // Include d2 == 0.25 (dist == RADIUS is kept by the reference):
    // gate on d2 < nextafter(0.25f) == 0.250000015f.
    const float RGATE = 0.250000015f;
    float lim = RGATE;

    for (int j = 0; j < NN; ++j) {
        const float4 p = spts[j];  // broadcast LDS.128 (all lanes same addr)
        float t = fmaf(qz, p.z, fmaf(qy, p.y, qx * p.x));
        float d2 = fmaf(-2.0f, t, qsq + p.w);
        d2 = fmaxf(d2, 0.0f);  // match sqrt(max(d2,0)) ordering (self -> 0)

        if (d2 < lim) {
            // Branchless insertion: predicates are all independent (ILP),
            // then a parallel shift network. Strict < keeps the earlier
            // (lower) index on ties, matching jax.lax.top_k.
            bool c[KK];
#pragma unroll
            for (int s = 0; s < KK; ++s) c[s] = d2 < dk[s];
#pragma unroll
            for (int s = KK - 1; s >= 1; --s) {
                dk[s] = c[s - 1] ? dk[s - 1] : (c[s] ? d2 : dk[s]);
                ik[s] = c[s - 1] ? ik[s - 1] : (c[s] ? j : ik[s]);
            }
            dk[0] = c[0] ? d2 : dk[0];
            ik[0] = c[0] ? j : ik[0];
            lim = fminf(dk[KK - 1], RGATE);
        }
    }

    // Epilogue: sum of flow-difference norms over the selected neighbors.
    const float fx = flb[3 * qi + 0];
    const float fy = flb[3 * qi + 1];
    const float fz = flb[3 * qi + 2];
    float acc = 0.0f;
#pragma unroll
    for (int s = 0; s < KK; ++s) {
        const int j = ik[s];
        float dx = fx - flb[3 * j + 0];
        float dy = fy - flb[3 * j + 1];
        float dz = fz - flb[3 * j + 2];
        acc += __fsqrt_rn(fmaf(dx, dx, fmaf(dy, dy, dz * dz)));
    }

    // Block reduction (reuse the SMEM buffer; everyone is done reading spts).
    __syncthreads();
    float* red = (float*)spts;
    red[threadIdx.x] = acc;
    __syncthreads();
#pragma unroll
    for (int s = TPB / 2; s > 0; s >>= 1) {
        if (threadIdx.x < s) red[threadIdx.x] += red[threadIdx.x + s];
        __syncthreads();
    }
    if (threadIdx.x == 0)
        g_partials[blockIdx.y * gridDim.x + blockIdx.x] = red[0];
}

__global__ void knn_finalize_kernel(float* __restrict__ out) {
    __shared__ float red[(NN / TPB) * BB];
    const int tid = threadIdx.x;
    red[tid] = g_partials[tid];
    __syncthreads();
#pragma unroll
    for (int s = (NN / TPB) * BB / 2; s > 0; s >>= 1) {
        if (tid < s) red[tid] += red[tid + s];
        __syncthreads();
    }
    if (tid == 0)
        out[0] = red[0] * (1.0f / (float)((size_t)BB * NN * KK));
}

extern "C" void kernel_launch(void* const* d_in, const int* in_sizes, int n_in,
                              void* d_out, int out_size) {
    const float* pc = (const float*)d_in[0];
    const float* flow = (const float*)d_in[1];

    cudaFuncSetAttribute(knn_loss_kernel,
                         cudaFuncAttributeMaxDynamicSharedMemorySize,
                         NN * sizeof(float4));

    dim3 grid(NN / TPB, BB);
    knn_loss_kernel<<<grid, TPB, NN * sizeof(float4)>>>(pc, flow);
    knn_finalize_kernel<<<1, (NN / TPB) * BB>>>((float*)d_out);
}

// round 2
// speedup vs baseline: 2.5421x; 2.5421x over previous
#include <cuda_runtime.h>

// KnnLoss via spatial grid: B=4, N=8192, C=3, K=16, RADIUS=0.5, L2.
// Only neighbors with d<=RADIUS contribute (others are replaced by self ->
// zero). Bin points into 32^3 cells of size RADIUS; every contributing pair
// lies within +/-1 cell. Per query: top-16 insert over ~620 candidates
// instead of 8192.

#define BB 4
#define NN 8192
#define KK 16
#define GRID 32
#define NCELLS (GRID * GRID * GRID)
#define TPB_MAIN 128
#define NPART (NN / TPB_MAIN)  // 64 partials per batch

__device__ int g_cellid[BB * NN];
__device__ int g_counts[BB * NCELLS];
__device__ int g_offsets[BB * (NCELLS + 1)];
__device__ int g_cursor[BB * NCELLS];
__device__ float4 g_sorted[BB * NN];
__device__ float g_partials[BB * NPART];

__device__ __forceinline__ int cell_coord(float v) {
    int c = (int)floorf((v + 8.0f) * 2.0f);
    return min(max(c, 0), GRID - 1);
}

// ---- 1. per-point cell id + histogram (counts pre-zeroed by memsetAsync) ----
__global__ void build_cells_kernel(const float* __restrict__ pc) {
    int t = blockIdx.x * blockDim.x + threadIdx.x;
    if (t >= BB * NN) return;
    int b = t / NN, n = t % NN;
    const float* p = pc + (size_t)b * NN * 3 + 3 * n;
    int cx = cell_coord(p[0]), cy = cell_coord(p[1]), cz = cell_coord(p[2]);
    int cell = (cz * GRID + cy) * GRID + cx;
    g_cellid[t] = cell;
    atomicAdd(&g_counts[b * NCELLS + cell], 1);
}

// ---- 2. exclusive scan of counts -> offsets (one CTA per batch) ----
__global__ __launch_bounds__(1024) void scan_kernel() {
    __shared__ int ssum[1024];
    const int b = blockIdx.x;
    const int t = threadIdx.x;
    const int* cnt = g_counts + b * NCELLS;
    int* off = g_offsets + b * (NCELLS + 1);
    int* cur = g_cursor + b * NCELLS;

    const int ITEMS = NCELLS / 1024;  // 32
    int local[ITEMS];
    int run = 0;
#pragma unroll
    for (int i = 0; i < ITEMS; ++i) {
        local[i] = run;                 // exclusive within thread
        run += cnt[t * ITEMS + i];
    }
    ssum[t] = run;
    __syncthreads();
    // Hillis-Steele inclusive scan over 1024 thread totals
    for (int o = 1; o < 1024; o <<= 1) {
        int v = (t >= o) ? ssum[t - o] : 0;
        __syncthreads();
        ssum[t] += v;
        __syncthreads();
    }
    int excl = ssum[t] - run;
#pragma unroll
    for (int i = 0; i < ITEMS; ++i) {
        int v = excl + local[i];
        off[t * ITEMS + i] = v;
        cur[t * ITEMS + i] = v;
    }
    if (t == 1023) off[NCELLS] = excl + run;  // = NN
}

// ---- 3. scatter points into cell-sorted order (idx packed into .w) ----
__global__ void scatter_kernel(const float* __restrict__ pc) {
    int t = blockIdx.x * blockDim.x + threadIdx.x;
    if (t >= BB * NN) return;
    int b = t / NN, n = t % NN;
    const float* p = pc + (size_t)b * NN * 3 + 3 * n;
    int cell = g_cellid[t];
    int pos = atomicAdd(&g_cursor[b * NCELLS + cell], 1);
    g_sorted[b * NN + pos] = make_float4(p[0], p[1], p[2], __int_as_float(n));
}

// ---- 4. main: radius-gated top-16 over 27-cell neighborhood ----
__global__ __launch_bounds__(TPB_MAIN) void knn_loss_kernel(
    const float* __restrict__ flow) {
    const int b = blockIdx.y;
    const int sp = blockIdx.x * TPB_MAIN + threadIdx.x;  // cell-sorted position
    const float4* __restrict__ sb = g_sorted + b * NN;
    const int* __restrict__ ob = g_offsets + b * (NCELLS + 1);
    const float* __restrict__ flb = flow + (size_t)b * NN * 3;

    const float4 me = sb[sp];
    const int qi = __float_as_int(me.w);
    const int cx = cell_coord(me.x), cy = cell_coord(me.y), cz = cell_coord(me.z);

    float dk[KK];
    int ik[KK];
#pragma unroll
    for (int s = 0; s < KK; ++s) { dk[s] = 3.0e38f; ik[s] = qi; }

    const float RGATE = 0.250000015f;  // keep d2 == 0.25 (dist == RADIUS kept)
    float lim = RGATE;

    const int x0 = max(cx - 1, 0);
    const int x1 = min(cx + 1, GRID - 1);
#pragma unroll
    for (int dz = -1; dz <= 1; ++dz) {
        int z2 = cz + dz;
        if ((unsigned)z2 >= (unsigned)GRID) continue;
#pragma unroll
        for (int dy = -1; dy <= 1; ++dy) {
            int y2 = cy + dy;
            if ((unsigned)y2 >= (unsigned)GRID) continue;
            int base = (z2 * GRID + y2) * GRID;
            int s = ob[base + x0];
            int e = ob[base + x1 + 1];
            for (int k = s; k < e; ++k) {
                float4 p = sb[k];
                float ddx = me.x - p.x;
                float ddy = me.y - p.y;
                float ddz = me.z - p.z;
                float d2 = fmaf(ddx, ddx, fmaf(ddy, ddy, ddz * ddz));
                if (d2 < lim) {
                    int j = __float_as_int(p.w);
                    bool c[KK];
#pragma unroll
                    for (int s2 = 0; s2 < KK; ++s2) c[s2] = d2 < dk[s2];
#pragma unroll
                    for (int s2 = KK - 1; s2 >= 1; --s2) {
                        dk[s2] = c[s2 - 1] ? dk[s2 - 1] : (c[s2] ? d2 : dk[s2]);
                        ik[s2] = c[s2 - 1] ? ik[s2 - 1] : (c[s2] ? j : ik[s2]);
                    }
                    dk[0] = c[0] ? d2 : dk[0];
                    ik[0] = c[0] ? j : ik[0];
                    lim = fminf(dk[KK - 1], RGATE);
                }
            }
        }
    }

    // Epilogue: sum of flow-difference norms over selected neighbors.
    const float fx = flb[3 * qi + 0];
    const float fy = flb[3 * qi + 1];
    const float fz = flb[3 * qi + 2];
    float acc = 0.0f;
#pragma unroll
    for (int s = 0; s < KK; ++s) {
        const int j = ik[s];
        float ddx = fx - flb[3 * j + 0];
        float ddy = fy - flb[3 * j + 1];
        float ddz = fz - flb[3 * j + 2];
        acc += __fsqrt_rn(fmaf(ddx, ddx, fmaf(ddy, ddy, ddz * ddz)));
    }

    // Block reduction: warp shuffles + smem across 4 warps.
    __shared__ float wsum[TPB_MAIN / 32];
#pragma unroll
    for (int o = 16; o > 0; o >>= 1)
        acc += __shfl_xor_sync(0xFFFFFFFFu, acc, o);
    if ((threadIdx.x & 31) == 0) wsum[threadIdx.x >> 5] = acc;
    __syncthreads();
    if (threadIdx.x == 0) {
        float s = 0.0f;
#pragma unroll
        for (int w = 0; w < TPB_MAIN / 32; ++w) s += wsum[w];
        g_partials[b * NPART + blockIdx.x] = s;
    }
}

// ---- 5. finalize ----
__global__ void knn_finalize_kernel(float* __restrict__ out) {
    __shared__ float red[BB * NPART];
    const int tid = threadIdx.x;
    red[tid] = g_partials[tid];
    __syncthreads();
#pragma unroll
    for (int s = BB * NPART / 2; s > 0; s >>= 1) {
        if (tid < s) red[tid] += red[tid + s];
        __syncthreads();
    }
    if (tid == 0)
        out[0] = red[0] * (1.0f / (float)((size_t)BB * NN * KK));
}

extern "C" void kernel_launch(void* const* d_in, const int* in_sizes, int n_in,
                              void* d_out, int out_size) {
    const float* pc = (const float*)d_in[0];
    const float* flow = (const float*)d_in[1];

    void* counts_ptr = nullptr;
    cudaGetSymbolAddress(&counts_ptr, g_counts);
    cudaMemsetAsync(counts_ptr, 0, BB * NCELLS * sizeof(int), 0);

    const int total = BB * NN;
    build_cells_kernel<<<(total + 255) / 256, 256>>>(pc);
    scan_kernel<<<BB, 1024>>>();
    scatter_kernel<<<(total + 255) / 256, 256>>>(pc);

    dim3 grid(NN / TPB_MAIN, BB);
    knn_loss_kernel<<<grid, TPB_MAIN>>>(flow);
    knn_finalize_kernel<<<1, BB * NPART>>>((float*)d_out);
}

// round 3
// speedup vs baseline: 5.0254x; 1.9769x over previous
#include <cuda_runtime.h>

// KnnLoss via spatial grid, 4 threads per query:
// B=4, N=8192, C=3, K=16, RADIUS=0.5, L2.
// Neighbors beyond RADIUS are replaced by self (zero contribution), so only
// the <=16 nearest in-radius neighbors matter. 16^3 grid over [-4,4]
// (cell = 0.5, clamped; clamping is monotone so in-radius pairs stay within
// +/-1 cell). Each query's candidate stream is split across 4 lanes; the
// 4 partial top-16 lists are fused via a distance-only bitonic threshold
// (tau = 16th smallest of the union); each lane then accumulates its own
// passing slots.

#define BB 4
#define NN 8192
#define KK 16
#define GRID 16
#define NCELLS (GRID * GRID * GRID)  // 4096
#define GQ 4                         // threads per query
#define TPB_MAIN 128
#define QPB (TPB_MAIN / GQ)          // 32 queries per CTA
#define NPART (NN / QPB)             // 256 CTAs per batch

__device__ int g_cellrank[BB * NN];  // cell | (rank << 12)
__device__ int g_counts[BB * NCELLS];
__device__ int g_offsets[BB * (NCELLS + 1)];
__device__ float4 g_sorted[BB * NN];
__device__ float g_partials[BB * NPART];

__device__ __forceinline__ int cell_coord(float v) {
    int c = (int)floorf((v + 4.0f) * 2.0f);
    return min(max(c, 0), GRID - 1);
}

// ---- 1. cell id + histogram (counts pre-zeroed); rank captured here ----
__global__ void build_cells_kernel(const float* __restrict__ pc) {
    int t = blockIdx.x * blockDim.x + threadIdx.x;
    if (t >= BB * NN) return;
    int b = t >> 13, n = t & (NN - 1);
    const float* p = pc + (size_t)b * NN * 3 + 3 * n;
    int cell = (cell_coord(p[2]) * GRID + cell_coord(p[1])) * GRID +
               cell_coord(p[0]);
    int rank = atomicAdd(&g_counts[b * NCELLS + cell], 1);
    g_cellrank[t] = cell | (rank << 12);
}

// ---- 2. exclusive scan (one CTA/batch, shfl-based, 2 barriers) ----
__global__ __launch_bounds__(512) void scan_kernel() {
    __shared__ int warp_tot[16];
    const int b = blockIdx.x, t = threadIdx.x;
    const int* cnt = g_counts + b * NCELLS;
    int* off = g_offsets + b * (NCELLS + 1);
    const int ITEMS = NCELLS / 512;  // 8
    int local[ITEMS];
    int run = 0;
#pragma unroll
    for (int i = 0; i < ITEMS; ++i) {
        local[i] = run;
        run += cnt[t * ITEMS + i];
    }
    int lane = t & 31, w = t >> 5;
    int v = run;
#pragma unroll
    for (int o = 1; o < 32; o <<= 1) {
        int u = __shfl_up_sync(0xFFFFFFFFu, v, o);
        if (lane >= o) v += u;
    }
    if (lane == 31) warp_tot[w] = v;
    __syncthreads();
    if (w == 0 && lane < 16) {
        int x = warp_tot[lane];
#pragma unroll
        for (int o = 1; o < 16; o <<= 1) {
            int u = __shfl_up_sync(0x0000FFFFu, x, o);
            if (lane >= o) x += u;
        }
        warp_tot[lane] = x;
    }
    __syncthreads();
    int excl = v - run + (w > 0 ? warp_tot[w - 1] : 0);
#pragma unroll
    for (int i = 0; i < ITEMS; ++i) off[t * ITEMS + i] = excl + local[i];
    if (t == 511) off[NCELLS] = excl + run;  // = NN
}

// ---- 3. scatter into cell-sorted order (atomic-free) ----
__global__ void scatter_kernel(const float* __restrict__ pc) {
    int t = blockIdx.x * blockDim.x + threadIdx.x;
    if (t >= BB * NN) return;
    int b = t >> 13, n = t & (NN - 1);
    const float* p = pc + (size_t)b * NN * 3 + 3 * n;
    int cr = g_cellrank[t];
    int cell = cr & (NCELLS - 1), rank = cr >> 12;
    int pos = g_offsets[b * (NCELLS + 1) + cell] + rank;
    g_sorted[b * NN + pos] = make_float4(p[0], p[1], p[2], __int_as_float(n));
}

// ---- 4. main: 4 lanes/query, radius-gated top-16, tau-threshold fuse ----
__global__ __launch_bounds__(TPB_MAIN) void knn_loss_kernel(
    const float* __restrict__ flow) {
    const int b = blockIdx.y;
    const int tid = threadIdx.x;
    const int sub = tid & (GQ - 1);
    const int sp = blockIdx.x * QPB + (tid >> 2);  // cell-sorted position
    const float4* __restrict__ sb = g_sorted + b * NN;
    const int* __restrict__ ob = g_offsets + b * (NCELLS + 1);
    const float* __restrict__ flb = flow + (size_t)b * NN * 3;

    const float4 me = sb[sp];
    const int qi = __float_as_int(me.w);
    const int cx = cell_coord(me.x), cy = cell_coord(me.y),
              cz = cell_coord(me.z);

    float dk[KK];
    int ik[KK];
#pragma unroll
    for (int s = 0; s < KK; ++s) { dk[s] = 3.0e38f; ik[s] = qi; }

    // Keep d2 values whose sqrt rounds to <= 0.5: d2 <= 0.25 + 2^-24.
    // Gate with strict < against the next float up (0.250000089).
    const float RGATE = 0.2500001f;
    float lim = RGATE;

    const int x0 = max(cx - 1, 0);
    const int x1 = min(cx + 1, GRID - 1);
#pragma unroll
    for (int dz = -1; dz <= 1; ++dz) {
        int z2 = cz + dz;
        if ((unsigned)z2 >= (unsigned)GRID) continue;
#pragma unroll
        for (int dy = -1; dy <= 1; ++dy) {
            int y2 = cy + dy;
            if ((unsigned)y2 >= (unsigned)GRID) continue;
            int base = (z2 * GRID + y2) * GRID;
            int s0 = ob[base + x0];
            int e0 = ob[base + x1 + 1];
            for (int k = s0 + sub; k < e0; k += GQ) {
                float4 p = sb[k];
                float ddx = me.x - p.x;
                float ddy = me.y - p.y;
                float ddz = me.z - p.z;
                float d2 = fmaf(ddx, ddx, fmaf(ddy, ddy, ddz * ddz));
                if (d2 < lim) {
                    int j = __float_as_int(p.w);
                    bool c[KK];
#pragma unroll
                    for (int s2 = 0; s2 < KK; ++s2) c[s2] = d2 < dk[s2];
#pragma unroll
                    for (int s2 = KK - 1; s2 >= 1; --s2) {
                        dk[s2] = c[s2 - 1] ? dk[s2 - 1] : (c[s2] ? d2 : dk[s2]);
                        ik[s2] = c[s2 - 1] ? ik[s2 - 1] : (c[s2] ? j : ik[s2]);
                    }
                    dk[0] = c[0] ? d2 : dk[0];
                    ik[0] = c[0] ? j : ik[0];
                    lim = fminf(dk[KK - 1], RGATE);
                }
            }
        }
    }

    __syncwarp();
    // Fuse 4 per-lane sorted lists into a threshold tau (16th smallest of
    // the union). Stage A (xor 1): bitonic half-merge + clean sort.
    float m[KK];
#pragma unroll
    for (int i = 0; i < KK; ++i) {
        float o = __shfl_xor_sync(0xFFFFFFFFu, dk[KK - 1 - i], 1);
        m[i] = fminf(dk[i], o);
    }
#pragma unroll
    for (int d = KK / 2; d >= 1; d >>= 1) {
#pragma unroll
        for (int i = 0; i < KK; ++i) {
            if ((i & d) == 0) {
                float a = m[i], cc = m[i + d];
                m[i] = fminf(a, cc);
                m[i + d] = fmaxf(a, cc);
            }
        }
    }
    // Stage B (xor 2): tau = max of elementwise mins (no sort needed).
    float tau = 0.0f;
#pragma unroll
    for (int i = 0; i < KK; ++i) {
        float o = __shfl_xor_sync(0xFFFFFFFFu, m[KK - 1 - i], 2);
        tau = fmaxf(tau, fminf(m[i], o));
    }

    // Epilogue: each lane accumulates its own slots with dk <= tau.
    // Empty slots (dk=3e38, ik=qi) pass only when tau=3e38 and contribute 0.
    const float fx = flb[3 * qi + 0];
    const float fy = flb[3 * qi + 1];
    const float fz = flb[3 * qi + 2];
    float acc = 0.0f;
#pragma unroll
    for (int s = 0; s < KK; ++s) {
        if (dk[s] <= tau) {
            const int j = ik[s];
            float ddx = fx - flb[3 * j + 0];
            float ddy = fy - flb[3 * j + 1];
            float ddz = fz - flb[3 * j + 2];
            acc += __fsqrt_rn(fmaf(ddx, ddx, fmaf(ddy, ddy, ddz * ddz)));
        }
    }

    // Block reduction (lane partials are disjoint, just sum everything).
    __shared__ float wsum[TPB_MAIN / 32];
#pragma unroll
    for (int o = 16; o > 0; o >>= 1)
        acc += __shfl_xor_sync(0xFFFFFFFFu, acc, o);
    if ((tid & 31) == 0) wsum[tid >> 5] = acc;
    __syncthreads();
    if (tid == 0) {
        float s = 0.0f;
#pragma unroll
        for (int w = 0; w < TPB_MAIN / 32; ++w) s += wsum[w];
        g_partials[b * NPART + blockIdx.x] = s;
    }
}

// ---- 5. finalize ----
__global__ void knn_finalize_kernel(float* __restrict__ out) {
    __shared__ float red[BB * NPART];
    const int tid = threadIdx.x;
    red[tid] = g_partials[tid];
    __syncthreads();
#pragma unroll
    for (int s = BB * NPART / 2; s > 0; s >>= 1) {
        if (tid < s) red[tid] += red[tid + s];
        __syncthreads();
    }
    if (tid == 0)
        out[0] = red[0] * (1.0f / (float)((size_t)BB * NN * KK));
}

extern "C" void kernel_launch(void* const* d_in, const int* in_sizes, int n_in,
                              void* d_out, int out_size) {
    const float* pc = (const float*)d_in[0];
    const float* flow = (const float*)d_in[1];

    void* counts_ptr = nullptr;
    cudaGetSymbolAddress(&counts_ptr, g_counts);
    cudaMemsetAsync(counts_ptr, 0, BB * NCELLS * sizeof(int), 0);

    const int total = BB * NN;
    build_cells_kernel<<<(total + 255) / 256, 256>>>(pc);
    scan_kernel<<<BB, 512>>>();
    scatter_kernel<<<(total + 255) / 256, 256>>>(pc);

    dim3 grid(NN / QPB, BB);
    knn_loss_kernel<<<grid, TPB_MAIN>>>(flow);
    knn_finalize_kernel<<<1, BB * NPART>>>((float*)d_out);
}

// round 4
// speedup vs baseline: 6.7011x; 1.3334x over previous
#include <cuda_runtime.h>

// KnnLoss via spatial grid, 8 threads/query, packed int keys:
// B=4, N=8192, C=3, K=16, RADIUS=0.5, L2.
// Out-of-radius neighbors are replaced by self (zero loss contribution), so
// only the <=16 nearest in-radius neighbors matter. 16^3 grid (cell=0.5,
// clamped, monotone => in-radius pairs within +/-1 cell). Each query's
// candidate stream splits over 8 lanes. Distances are quantized to 17 bits
// and packed with the 13-bit index into one int key: the top-16 insert is a
// single-array SEL network and tie-break = lower index, matching top_k.
// Lane lists fuse via bitonic merges into tau = 16th-smallest key of the
// union; each lane accumulates flow norms for its own slots with key<=tau.

#define BB 4
#define NN 8192
#define KK 16
#define GRID 16
#define NCELLS (GRID * GRID * GRID)  // 4096
#define GQ 8                         // threads per query
#define TPB_MAIN 128
#define QPB (TPB_MAIN / GQ)          // 16 queries per CTA
#define NPART (NN / QPB)             // 512 CTAs per batch

__device__ int g_cellrank[BB * NN];  // cell | (rank << 12)
__device__ int g_counts[BB * NCELLS];
__device__ int g_offsets[BB * (NCELLS + 1)];
__device__ float4 g_sorted[BB * NN];
__device__ float g_partials[BB * NPART];

__device__ __forceinline__ int cell_coord(float v) {
    int c = (int)floorf((v + 4.0f) * 2.0f);
    return min(max(c, 0), GRID - 1);
}

// ---- 1. cell id + histogram (counts pre-zeroed); rank captured here ----
__global__ void build_cells_kernel(const float* __restrict__ pc) {
    int t = blockIdx.x * blockDim.x + threadIdx.x;
    if (t >= BB * NN) return;
    int b = t >> 13, n = t & (NN - 1);
    const float* p = pc + (size_t)b * NN * 3 + 3 * n;
    int cell = (cell_coord(p[2]) * GRID + cell_coord(p[1])) * GRID +
               cell_coord(p[0]);
    int rank = atomicAdd(&g_counts[b * NCELLS + cell], 1);
    g_cellrank[t] = cell | (rank << 12);
}

// ---- 2. exclusive scan (one CTA/batch, shfl-based) ----
__global__ __launch_bounds__(512) void scan_kernel() {
    __shared__ int warp_tot[16];
    const int b = blockIdx.x, t = threadIdx.x;
    const int* cnt = g_counts + b * NCELLS;
    int* off = g_offsets + b * (NCELLS + 1);
    const int ITEMS = NCELLS / 512;  // 8
    int local[ITEMS];
    int run = 0;
#pragma unroll
    for (int i = 0; i < ITEMS; ++i) {
        local[i] = run;
        run += cnt[t * ITEMS + i];
    }
    int lane = t & 31, w = t >> 5;
    int v = run;
#pragma unroll
    for (int o = 1; o < 32; o <<= 1) {
        int u = __shfl_up_sync(0xFFFFFFFFu, v, o);
        if (lane >= o) v += u;
    }
    if (lane == 31) warp_tot[w] = v;
    __syncthreads();
    if (w == 0 && lane < 16) {
        int x = warp_tot[lane];
#pragma unroll
        for (int o = 1; o < 16; o <<= 1) {
            int u = __shfl_up_sync(0x0000FFFFu, x, o);
            if (lane >= o) x += u;
        }
        warp_tot[lane] = x;
    }
    __syncthreads();
    int excl = v - run + (w > 0 ? warp_tot[w - 1] : 0);
#pragma unroll
    for (int i = 0; i < ITEMS; ++i) off[t * ITEMS + i] = excl + local[i];
    if (t == 511) off[NCELLS] = excl + run;  // = NN
}

// ---- 3. scatter into cell-sorted order (atomic-free) ----
__global__ void scatter_kernel(const float* __restrict__ pc) {
    int t = blockIdx.x * blockDim.x + threadIdx.x;
    if (t >= BB * NN) return;
    int b = t >> 13, n = t & (NN - 1);
    const float* p = pc + (size_t)b * NN * 3 + 3 * n;
    int cr = g_cellrank[t];
    int cell = cr & (NCELLS - 1), rank = cr >> 12;
    int pos = g_offsets[b * (NCELLS + 1) + cell] + rank;
    g_sorted[b * NN + pos] = make_float4(p[0], p[1], p[2], __int_as_float(n));
}

// ---- 4. main: 8 lanes/query, packed-key top-16, tau fuse ----
__global__ __launch_bounds__(TPB_MAIN) void knn_loss_kernel(
    const float* __restrict__ flow) {
    const int b = blockIdx.y;
    const int tid = threadIdx.x;
    const int sub = tid & (GQ - 1);
    const int sp = blockIdx.x * QPB + (tid >> 3);  // cell-sorted position
    const float4* __restrict__ sb = g_sorted + b * NN;
    const int* __restrict__ ob = g_offsets + b * (NCELLS + 1);
    const float* __restrict__ flb = flow + (size_t)b * NN * 3;

    const float4 me = sb[sp];
    const int qi = __float_as_int(me.w);
    const int cx = cell_coord(me.x), cy = cell_coord(me.y),
              cz = cell_coord(me.z);

    // Sentinel decodes to self-index => zero contribution if selected.
    const int SENT = (0x3FFFF << 13) | qi;
    int kk[KK];
#pragma unroll
    for (int s = 0; s < KK; ++s) kk[s] = SENT;
    int lim = SENT;

    // Keep d2 whose sqrt rounds to <= 0.5 (d2 <= 0.25 + 2^-24).
    const float RGATE = 0.2500001f;

    const int x0 = max(cx - 1, 0);
    const int x1 = min(cx + 1, GRID - 1);
#pragma unroll
    for (int dz = -1; dz <= 1; ++dz) {
        int z2 = cz + dz;
        if ((unsigned)z2 >= (unsigned)GRID) continue;
#pragma unroll
        for (int dy = -1; dy <= 1; ++dy) {
            int y2 = cy + dy;
            if ((unsigned)y2 >= (unsigned)GRID) continue;
            int base = (z2 * GRID + y2) * GRID;
            int s0 = ob[base + x0];
            int e0 = ob[base + x1 + 1];
            for (int k = s0 + sub; k < e0; k += GQ) {
                float4 p = sb[k];
                float ddx = me.x - p.x;
                float ddy = me.y - p.y;
                float ddz = me.z - p.z;
                float d2 = fmaf(ddx, ddx, fmaf(ddy, ddy, ddz * ddz));
                if (d2 < RGATE) {
                    // 17-bit quantized distance | 13-bit index.
                    int key = ((int)(d2 * 262144.0f) << 13) |
                              __float_as_int(p.w);
                    if (key < lim) {
                        bool c[KK];
#pragma unroll
                        for (int s2 = 0; s2 < KK; ++s2) c[s2] = key < kk[s2];
#pragma unroll
                        for (int s2 = KK - 1; s2 >= 1; --s2)
                            kk[s2] = c[s2 - 1] ? kk[s2 - 1]
                                               : (c[s2] ? key : kk[s2]);
                        kk[0] = c[0] ? key : kk[0];
                        lim = kk[KK - 1];
                    }
                }
            }
        }
    }

    __syncwarp();
    // Fuse 8 sorted lists: two full bitonic merges (xor 1, xor 2), then a
    // threshold-only stage (xor 4). tau = 16th smallest key of the union.
    int m[KK];
#pragma unroll
    for (int i = 0; i < KK; ++i) {
        int o = __shfl_xor_sync(0xFFFFFFFFu, kk[KK - 1 - i], 1);
        m[i] = min(kk[i], o);
    }
#pragma unroll
    for (int d = KK / 2; d >= 1; d >>= 1)
#pragma unroll
        for (int i = 0; i < KK; ++i)
            if ((i & d) == 0) {
                int a = m[i], cc = m[i + d];
                m[i] = min(a, cc);
                m[i + d] = max(a, cc);
            }
#pragma unroll
    for (int i = 0; i < KK; ++i) {
        int o = __shfl_xor_sync(0xFFFFFFFFu, m[KK - 1 - i], 2);
        // reuse kk as scratch for the second merge result
        kk[i] = min(m[i], o);
    }
#pragma unroll
    for (int d = KK / 2; d >= 1; d >>= 1)
#pragma unroll
        for (int i = 0; i < KK; ++i)
            if ((i & d) == 0) {
                int a = kk[i], cc = kk[i + d];
                kk[i] = min(a, cc);
                kk[i + d] = max(a, cc);
            }
    int tau = 0;
#pragma unroll
    for (int i = 0; i < KK; ++i) {
        int o = __shfl_xor_sync(0xFFFFFFFFu, kk[KK - 1 - i], 4);
        tau = max(tau, min(kk[i], o));
    }

    // Epilogue: each lane accumulates flow norms for its kk-level-2 slots...
    // NOTE: after the merges, per-lane slots no longer partition the union.
    // Use the ORIGINAL per-lane list: recompute is impossible (kk clobbered),
    // so we kept m free? m holds level-1 result (also merged). Instead we
    // re-filter with the level-2 list but only on lanes where sub&3==0 would
    // double count. Correct approach: each (xor-2) pair's level-2 list holds
    // the union of 4 lanes; lanes sub%4==0 own it exclusively.
    // kk (level-2, sorted) on lanes with (sub & 1) == 0 and (sub & 2) == 0
    // contains the 16 smallest of lanes {sub..sub+3}? No: every lane holds a
    // valid level-2 merged list of its xor-1/xor-2 group; all 4 lanes of a
    // group hold IDENTICAL lists. So let only one lane per group (sub%4==0)
    // accumulate its 16 slots; groups are disjoint; union of two group lists
    // covers the true top-16 (tau filters to exactly the global top-16).
    float acc = 0.0f;
    if ((sub & 3) == 0) {
        const float fx = flb[3 * qi + 0];
        const float fy = flb[3 * qi + 1];
        const float fz = flb[3 * qi + 2];
#pragma unroll
        for (int s = 0; s < KK; ++s) {
            if (kk[s] <= tau) {
                const int j = kk[s] & (NN - 1);
                float ddx = fx - flb[3 * j + 0];
                float ddy = fy - flb[3 * j + 1];
                float ddz = fz - flb[3 * j + 2];
                acc += __fsqrt_rn(fmaf(ddx, ddx, fmaf(ddy, ddy, ddz * ddz)));
            }
        }
    }

    // Block reduction.
    __shared__ float wsum[TPB_MAIN / 32];
#pragma unroll
    for (int o = 16; o > 0; o >>= 1)
        acc += __shfl_xor_sync(0xFFFFFFFFu, acc, o);
    if ((tid & 31) == 0) wsum[tid >> 5] = acc;
    __syncthreads();
    if (tid == 0) {
        float s = 0.0f;
#pragma unroll
        for (int w = 0; w < TPB_MAIN / 32; ++w) s += wsum[w];
        g_partials[b * NPART + blockIdx.x] = s;
    }
}

// ---- 5. finalize (2048 partials, 1024 threads x 2) ----
__global__ __launch_bounds__(1024) void knn_finalize_kernel(
    float* __restrict__ out) {
    __shared__ float red[1024];
    const int tid = threadIdx.x;
    red[tid] = g_partials[tid] + g_partials[tid + 1024];
    __syncthreads();
#pragma unroll
    for (int s = 512; s > 0; s >>= 1) {
        if (tid < s) red[tid] += red[tid + s];
        __syncthreads();
    }
    if (tid == 0)
        out[0] = red[0] * (1.0f / (float)((size_t)BB * NN * KK));
}

extern "C" void kernel_launch(void* const* d_in, const int* in_sizes, int n_in,
                              void* d_out, int out_size) {
    const float* pc = (const float*)d_in[0];
    const float* flow = (const float*)d_in[1];

    void* counts_ptr = nullptr;
    cudaGetSymbolAddress(&counts_ptr, g_counts);
    cudaMemsetAsync(counts_ptr, 0, BB * NCELLS * sizeof(int), 0);

    const int total = BB * NN;
    build_cells_kernel<<<(total + 255) / 256, 256>>>(pc);
    scan_kernel<<<BB, 512>>>();
    scatter_kernel<<<(total + 255) / 256, 256>>>(pc);

    dim3 grid(NN / QPB, BB);
    knn_loss_kernel<<<grid, TPB_MAIN>>>(flow);
    knn_finalize_kernel<<<1, 1024>>>((float*)d_out);
}

// round 5
// speedup vs baseline: 7.3542x; 1.0975x over previous
#include <cuda_runtime.h>

// KnnLoss via spatial grid, warp-per-query, ballot-compact + tournament select:
// B=4, N=8192, C=3, K=16, RADIUS=0.5, L2.
// Out-of-radius neighbors are replaced by self (zero contribution), so only
// the <=16 nearest in-radius neighbors matter. 16^3 grid (cell=0.5, clamped,
// monotone => in-radius pairs stay within +/-1 cell).
// Phase 1: 32 lanes sweep the 27-cell neighborhood coalesced; in-radius keys
//   (17-bit quantized d2 | 13-bit idx => unique, tie=lower idx like top_k)
//   are ballot-compacted into a per-warp smem buffer (no sort, no atomics).
// Phase 2: 16 tournament rounds of __reduce_min_sync pick the top-16; round
//   r's winner parks on lane r.
// Phase 3: lanes 0..15 compute their flow norms in parallel; warp reduce.

#define BB 4
#define NN 8192
#define KK 16
#define GRID 16
#define NCELLS (GRID * GRID * GRID)  // 4096
#define TPB_MAIN 256
#define WPB (TPB_MAIN / 32)          // 8 warps = 8 queries per CTA
#define CAP 512                      // per-query candidate buffer (max ~330)
#define NPART (NN / WPB)             // 1024 CTAs per batch
#define IMAX 0x7FFFFFFF

__device__ int g_cellrank[BB * NN];  // cell | (rank << 12)
__device__ int g_counts[BB * NCELLS];
__device__ int g_offsets[BB * (NCELLS + 1)];
__device__ float4 g_sorted[BB * NN];
__device__ float g_partials[BB * NPART];

__device__ __forceinline__ int cell_coord(float v) {
    int c = (int)floorf((v + 4.0f) * 2.0f);
    return min(max(c, 0), GRID - 1);
}

// ---- 1. cell id + histogram (counts pre-zeroed); rank captured here ----
__global__ void build_cells_kernel(const float* __restrict__ pc) {
    int t = blockIdx.x * blockDim.x + threadIdx.x;
    if (t >= BB * NN) return;
    int b = t >> 13, n = t & (NN - 1);
    const float* p = pc + (size_t)b * NN * 3 + 3 * n;
    int cell = (cell_coord(p[2]) * GRID + cell_coord(p[1])) * GRID +
               cell_coord(p[0]);
    int rank = atomicAdd(&g_counts[b * NCELLS + cell], 1);
    g_cellrank[t] = cell | (rank << 12);
}

// ---- 2. exclusive scan (one CTA/batch, shfl-based) ----
__global__ __launch_bounds__(512) void scan_kernel() {
    __shared__ int warp_tot[16];
    const int b = blockIdx.x, t = threadIdx.x;
    const int* cnt = g_counts + b * NCELLS;
    int* off = g_offsets + b * (NCELLS + 1);
    const int ITEMS = NCELLS / 512;  // 8
    int local[ITEMS];
    int run = 0;
#pragma unroll
    for (int i = 0; i < ITEMS; ++i) {
        local[i] = run;
        run += cnt[t * ITEMS + i];
    }
    int lane = t & 31, w = t >> 5;
    int v = run;
#pragma unroll
    for (int o = 1; o < 32; o <<= 1) {
        int u = __shfl_up_sync(0xFFFFFFFFu, v, o);
        if (lane >= o) v += u;
    }
    if (lane == 31) warp_tot[w] = v;
    __syncthreads();
    if (w == 0 && lane < 16) {
        int x = warp_tot[lane];
#pragma unroll
        for (int o = 1; o < 16; o <<= 1) {
            int u = __shfl_up_sync(0x0000FFFFu, x, o);
            if (lane >= o) x += u;
        }
        warp_tot[lane] = x;
    }
    __syncthreads();
    int excl = v - run + (w > 0 ? warp_tot[w - 1] : 0);
#pragma unroll
    for (int i = 0; i < ITEMS; ++i) off[t * ITEMS + i] = excl + local[i];
    if (t == 511) off[NCELLS] = excl + run;  // = NN
}

// ---- 3. scatter into cell-sorted order (atomic-free) ----
__global__ void scatter_kernel(const float* __restrict__ pc) {
    int t = blockIdx.x * blockDim.x + threadIdx.x;
    if (t >= BB * NN) return;
    int b = t >> 13, n = t & (NN - 1);
    const float* p = pc + (size_t)b * NN * 3 + 3 * n;
    int cr = g_cellrank[t];
    int cell = cr & (NCELLS - 1), rank = cr >> 12;
    int pos = g_offsets[b * (NCELLS + 1) + cell] + rank;
    g_sorted[b * NN + pos] = make_float4(p[0], p[1], p[2], __int_as_float(n));
}

// ---- 4. main: warp per query ----
__global__ __launch_bounds__(TPB_MAIN) void knn_loss_kernel(
    const float* __restrict__ flow) {
    __shared__ int buf[WPB][CAP];
    __shared__ float cpart[WPB];

    const int b = blockIdx.y;
    const int w = threadIdx.x >> 5;
    const int lane = threadIdx.x & 31;
    const int sp = blockIdx.x * WPB + w;  // cell-sorted query position
    int* __restrict__ bw = buf[w];
    const float4* __restrict__ sb = g_sorted + b * NN;
    const int* __restrict__ ob = g_offsets + b * (NCELLS + 1);
    const float* __restrict__ flb = flow + (size_t)b * NN * 3;

    const float4 me = sb[sp];  // broadcast
    const int qi = __float_as_int(me.w);
    const int cx = cell_coord(me.x), cy = cell_coord(me.y),
              cz = cell_coord(me.z);

    // Keep d2 whose sqrt rounds to <= 0.5 (d2 <= 0.25 + 2^-24).
    const float RGATE = 0.2500001f;

    // Phase 1: coalesced sweep + ballot compaction into smem.
    int cnt = 0;  // warp-uniform
    const int x0 = max(cx - 1, 0);
    const int x1 = min(cx + 1, GRID - 1);
#pragma unroll
    for (int dz = -1; dz <= 1; ++dz) {
        int z2 = cz + dz;
        if ((unsigned)z2 >= (unsigned)GRID) continue;
#pragma unroll
        for (int dy = -1; dy <= 1; ++dy) {
            int y2 = cy + dy;
            if ((unsigned)y2 >= (unsigned)GRID) continue;
            int base = (z2 * GRID + y2) * GRID;
            int s0 = ob[base + x0];
            int e0 = ob[base + x1 + 1];
            for (int kb = s0; kb < e0; kb += 32) {
                int k = kb + lane;
                float4 p = make_float4(1e9f, 1e9f, 1e9f, 0.0f);
                if (k < e0) p = sb[k];
                float ddx = me.x - p.x;
                float ddy = me.y - p.y;
                float ddz = me.z - p.z;
                float d2 = fmaf(ddx, ddx, fmaf(ddy, ddy, ddz * ddz));
                bool inr = d2 < RGATE;
                unsigned mask = __ballot_sync(0xFFFFFFFFu, inr);
                if (inr) {
                    int key = ((int)(d2 * 262144.0f) << 13) |
                              __float_as_int(p.w);
                    int pos = cnt + __popc(mask & ((1u << lane) - 1u));
                    if (pos < CAP) bw[pos] = key;
                }
                cnt += __popc(mask);
            }
        }
    }
    cnt = min(cnt, CAP);
    __syncwarp();

    // Phase 2: 16 tournament rounds; round r's winner parks on lane r.
    const int R = min(cnt, KK);
    const int P = (cnt + 31) >> 5;
    int selkey = IMAX;
    for (int r = 0; r < R; ++r) {
        int mymin = IMAX, myidx = 0;
        for (int i = 0; i < P; ++i) {
            int k = lane + (i << 5);
            int v = (k < cnt) ? bw[k] : IMAX;
            if (v < mymin) { mymin = v; myidx = k; }
        }
        int gmin = __reduce_min_sync(0xFFFFFFFFu, mymin);
        if (mymin == gmin && gmin != IMAX) bw[myidx] = IMAX;  // unique keys
        if (lane == r) selkey = gmin;
        __syncwarp();
    }

    // Phase 3: lanes 0..R-1 hold the selected keys; parallel norms.
    float acc = 0.0f;
    if (selkey != IMAX) {
        const int j = selkey & (NN - 1);  // j==qi (self) => exact 0
        float ddx = flb[3 * qi + 0] - flb[3 * j + 0];
        float ddy = flb[3 * qi + 1] - flb[3 * j + 1];
        float ddz = flb[3 * qi + 2] - flb[3 * j + 2];
        acc = __fsqrt_rn(fmaf(ddx, ddx, fmaf(ddy, ddy, ddz * ddz)));
    }
#pragma unroll
    for (int o = 16; o > 0; o >>= 1)
        acc += __shfl_xor_sync(0xFFFFFFFFu, acc, o);
    if (lane == 0) cpart[w] = acc;
    __syncthreads();
    if (threadIdx.x == 0) {
        float s = 0.0f;
#pragma unroll
        for (int i = 0; i < WPB; ++i) s += cpart[i];
        g_partials[b * NPART + blockIdx.x] = s;
    }
}

// ---- 5. finalize (4096 partials, 1024 threads x 4) ----
__global__ __launch_bounds__(1024) void knn_finalize_kernel(
    float* __restrict__ out) {
    __shared__ float red[1024];
    const int tid = threadIdx.x;
    float s = 0.0f;
#pragma unroll
    for (int i = 0; i < BB * NPART / 1024; ++i)
        s += g_partials[tid + i * 1024];
    red[tid] = s;
    __syncthreads();
#pragma unroll
    for (int st = 512; st > 0; st >>= 1) {
        if (tid < st) red[tid] += red[tid + st];
        __syncthreads();
    }
    if (tid == 0)
        out[0] = red[0] * (1.0f / (float)((size_t)BB * NN * KK));
}

extern "C" void kernel_launch(void* const* d_in, const int* in_sizes, int n_in,
                              void* d_out, int out_size) {
    const float* pc = (const float*)d_in[0];
    const float* flow = (const float*)d_in[1];

    void* counts_ptr = nullptr;
    cudaGetSymbolAddress(&counts_ptr, g_counts);
    cudaMemsetAsync(counts_ptr, 0, BB * NCELLS * sizeof(int), 0);

    const int total = BB * NN;
    build_cells_kernel<<<(total + 255) / 256, 256>>>(pc);
    scan_kernel<<<BB, 512>>>();
    scatter_kernel<<<(total + 255) / 256, 256>>>(pc);

    dim3 grid(NN / WPB, BB);
    knn_loss_kernel<<<grid, TPB_MAIN>>>(flow);
    knn_finalize_kernel<<<1, 1024>>>((float*)d_out);
}

// round 6
// speedup vs baseline: 7.8109x; 1.0621x over previous
#include <cuda_runtime.h>

// KnnLoss via spatial grid, warp-per-query:
// B=4, N=8192, C=3, K=16, RADIUS=0.5, L2.
// Out-of-radius neighbors are replaced by self (zero contribution) => only
// the <=16 nearest in-radius neighbors matter. 16^3 grid (cell=0.5, clamped,
// monotone => in-radius pairs within +/-1 cell).
// Kernel 1 (4 CTAs): histogram (smem) + scan (smem, in-place) + scatter.
// Kernel 2: per query-warp: coalesced sweep with geometric row/corner trim,
//   ballot-compaction of packed keys (17-bit quantized d2 | 13-bit idx =>
//   unique, tie = lower idx like top_k), register-resident tournament
//   (REDUX.MIN over sorted 4-deep per-lane lists) for cnt<=128, smem
//   tournament otherwise; parallel flow norms; last CTA reduces partials.

#define BB 4
#define NN 8192
#define KK 16
#define GRID 16
#define NCELLS (GRID * GRID * GRID)  // 4096
#define TPB_MAIN 256
#define WPB (TPB_MAIN / 32)          // 8 queries per CTA
#define CAP 512
#define NPART (NN / WPB)             // 1024 CTAs per batch
#define NCTAS (BB * NPART)           // 4096
#define IMAX 0x7FFFFFFF
#define RGATE 0.2500001f             // keep d2 whose sqrt rounds to <= 0.5
#define GATE2 0.2500002f             // prune bound (extra fp slack)

__device__ int g_offsets[BB * (NCELLS + 1)];
__device__ float4 g_sorted[BB * NN];
__device__ float g_partials[NCTAS];
__device__ int g_done;  // zero-init; reset by last CTA each run

__device__ __forceinline__ int cell_coord(float v) {
    int c = (int)floorf((v + 4.0f) * 2.0f);
    return min(max(c, 0), GRID - 1);
}

// ---- 1. fused grid build: histogram + scan + scatter (one CTA per batch) ---
#define PPT (NN / 1024)  // 8 points per thread
__global__ __launch_bounds__(1024) void grid_build_kernel(
    const float* __restrict__ pc) {
    __shared__ int hist[NCELLS];  // counts -> (in-place) exclusive offsets
    __shared__ int wtot[32];
    const int b = blockIdx.x, t = threadIdx.x;
    const int lane = t & 31, w = t >> 5;

#pragma unroll
    for (int i = 0; i < NCELLS / 1024; ++i) hist[t + i * 1024] = 0;
    __syncthreads();

    const float* pcb = pc + (size_t)b * NN * 3;
    float px[PPT], py[PPT], pz[PPT];
    int cell[PPT], rank[PPT];
#pragma unroll
    for (int i = 0; i < PPT; ++i) {
        int n = t + i * 1024;
        px[i] = pcb[3 * n + 0];
        py[i] = pcb[3 * n + 1];
        pz[i] = pcb[3 * n + 2];
        cell[i] = (cell_coord(pz[i]) * GRID + cell_coord(py[i])) * GRID +
                  cell_coord(px[i]);
        rank[i] = atomicAdd(&hist[cell[i]], 1);
    }
    __syncthreads();

    // Exclusive scan of hist (4 items/thread, shfl two-level), in place.
    int local[4];
    int run = 0;
#pragma unroll
    for (int i = 0; i < 4; ++i) {
        local[i] = run;
        run += hist[t * 4 + i];
    }
    int v = run;
#pragma unroll
    for (int o = 1; o < 32; o <<= 1) {
        int u = __shfl_up_sync(0xFFFFFFFFu, v, o);
        if (lane >= o) v += u;
    }
    if (lane == 31) wtot[w] = v;
    __syncthreads();
    if (w == 0) {
        int x = wtot[lane];
#pragma unroll
        for (int o = 1; o < 32; o <<= 1) {
            int u = __shfl_up_sync(0xFFFFFFFFu, x, o);
            if (lane >= o) x += u;
        }
        wtot[lane] = x;
    }
    __syncthreads();
    int excl = v - run + (w > 0 ? wtot[w - 1] : 0);
    int* gob = g_offsets + b * (NCELLS + 1);
#pragma unroll
    for (int i = 0; i < 4; ++i) {
        int o2 = excl + local[i];
        hist[t * 4 + i] = o2;
        gob[t * 4 + i] = o2;
    }
    if (t == 1023) gob[NCELLS] = excl + run;  // = NN
    __syncthreads();

    // Scatter from registers.
    float4* sbb = g_sorted + b * NN;
#pragma unroll
    for (int i = 0; i < PPT; ++i) {
        int pos = hist[cell[i]] + rank[i];
        sbb[pos] = make_float4(px[i], py[i], pz[i],
                               __int_as_float(t + i * 1024));
    }
}

// ---- 2. main: warp per query; last CTA finalizes ----
__global__ __launch_bounds__(TPB_MAIN) void knn_loss_kernel(
    const float* __restrict__ flow, float* __restrict__ out) {
    __shared__ int buf[WPB][CAP];
    __shared__ float cpart[WPB];
    __shared__ int lastflag;

    const int b = blockIdx.y;
    const int w = threadIdx.x >> 5;
    const int lane = threadIdx.x & 31;
    const int sp = blockIdx.x * WPB + w;
    int* __restrict__ bw = buf[w];
    const float4* __restrict__ sb = g_sorted + b * NN;
    const int* __restrict__ ob = g_offsets + b * (NCELLS + 1);
    const float* __restrict__ flb = flow + (size_t)b * NN * 3;

    const float4 me = sb[sp];  // broadcast
    const int qi = __float_as_int(me.w);
    const int cx = cell_coord(me.x), cy = cell_coord(me.y),
              cz = cell_coord(me.z);

    // Per-axis band distances^2 (true lower bounds on d2 toward +/-1 cells).
    const float fx = fmaf((float)cx, -0.5f, me.x + 4.0f);
    const float fy = fmaf((float)cy, -0.5f, me.y + 4.0f);
    const float fz = fmaf((float)cz, -0.5f, me.z + 4.0f);
    const float fx2lo = fx * fx, fx2hi = (0.5f - fx) * (0.5f - fx);
    float dy2m[3], dz2m[3];
    dy2m[0] = fy * fy; dy2m[1] = 0.0f; dy2m[2] = (0.5f - fy) * (0.5f - fy);
    dz2m[0] = fz * fz; dz2m[1] = 0.0f; dz2m[2] = (0.5f - fz) * (0.5f - fz);

    // Phase 1: sweep + ballot compaction.
    int cnt = 0;  // warp-uniform
    const int x0 = max(cx - 1, 0);
    const int x1 = min(cx + 1, GRID - 1);
#pragma unroll
    for (int dz = -1; dz <= 1; ++dz) {
        int z2 = cz + dz;
        if ((unsigned)z2 >= (unsigned)GRID) continue;
#pragma unroll
        for (int dy = -1; dy <= 1; ++dy) {
            int y2 = cy + dy;
            if ((unsigned)y2 >= (unsigned)GRID) continue;
            float rd2 = dz2m[dz + 1] + dy2m[dy + 1];
            if (rd2 > GATE2) continue;  // whole row unreachable
            // Trim corner x-cells off the run ends when unreachable.
            int xl = (rd2 + fx2lo > GATE2) ? cx : x0;
            int xh = (rd2 + fx2hi > GATE2) ? cx : x1;
            int base = (z2 * GRID + y2) * GRID;
            int s0 = ob[base + xl];
            int e0 = ob[base + xh + 1];
            for (int kb = s0; kb < e0; kb += 32) {
                int k = kb + lane;
                float4 p = make_float4(1e9f, 1e9f, 1e9f, 0.0f);
                if (k < e0) p = sb[k];
                float ddx = me.x - p.x;
                float ddy = me.y - p.y;
                float ddz = me.z - p.z;
                float d2 = fmaf(ddx, ddx, fmaf(ddy, ddy, ddz * ddz));
                bool inr = d2 < RGATE;
                unsigned mask = __ballot_sync(0xFFFFFFFFu, inr);
                if (inr) {
                    int key = ((int)(d2 * 262144.0f) << 13) |
                              __float_as_int(p.w);
                    int pos = cnt + __popc(mask & ((1u << lane) - 1u));
                    if (pos < CAP) bw[pos] = key;
                }
                cnt += __popc(mask);
            }
        }
    }
    cnt = min(cnt, CAP);
    __syncwarp();

    // Phase 2: top-16 selection; round r's winner parks on lane r.
    const int R = min(cnt, KK);
    int selkey = IMAX;
    if (cnt <= 128) {
        // Register-resident: <=4 items/lane, sorted ascending, shift-out.
        int v0 = (lane < cnt) ? bw[lane] : IMAX;
        int v1 = (lane + 32 < cnt) ? bw[lane + 32] : IMAX;
        int v2 = (lane + 64 < cnt) ? bw[lane + 64] : IMAX;
        int v3 = (lane + 96 < cnt) ? bw[lane + 96] : IMAX;
        int t0;
        t0 = min(v0, v1); v1 = max(v0, v1); v0 = t0;  // (0,1)
        t0 = min(v2, v3); v3 = max(v2, v3); v2 = t0;  // (2,3)
        t0 = min(v0, v2); v2 = max(v0, v2); v0 = t0;  // (0,2)
        t0 = min(v1, v3); v3 = max(v1, v3); v1 = t0;  // (1,3)
        t0 = min(v1, v2); v2 = max(v1, v2); v1 = t0;  // (1,2)
        for (int r = 0; r < R; ++r) {
            int gmin = __reduce_min_sync(0xFFFFFFFFu, v0);
            bool won = (v0 == gmin);  // keys unique => exactly one winner
            v0 = won ? v1 : v0;
            v1 = won ? v2 : v1;
            v2 = won ? v3 : v2;
            v3 = won ? IMAX : v3;
            if (lane == r) selkey = gmin;
        }
    } else {
        const int P = (cnt + 31) >> 5;
        for (int r = 0; r < R; ++r) {
            int mymin = IMAX, myidx = 0;
            for (int i = 0; i < P; ++i) {
                int k = lane + (i << 5);
                int vv = (k < cnt) ? bw[k] : IMAX;
                if (vv < mymin) { mymin = vv; myidx = k; }
            }
            int gmin = __reduce_min_sync(0xFFFFFFFFu, mymin);
            if (mymin == gmin && gmin != IMAX) bw[myidx] = IMAX;
            if (lane == r) selkey = gmin;
            __syncwarp();
        }
    }

    // Phase 3: lanes 0..R-1 hold selected keys; parallel norms + reduce.
    float acc = 0.0f;
    if (selkey != IMAX) {
        const int j = selkey & (NN - 1);  // j==qi (self) => exact 0
        float ddx = flb[3 * qi + 0] - flb[3 * j + 0];
        float ddy = flb[3 * qi + 1] - flb[3 * j + 1];
        float ddz = flb[3 * qi + 2] - flb[3 * j + 2];
        acc = __fsqrt_rn(fmaf(ddx, ddx, fmaf(ddy, ddy, ddz * ddz)));
    }
#pragma unroll
    for (int o = 16; o > 0; o >>= 1)
        acc += __shfl_xor_sync(0xFFFFFFFFu, acc, o);
    if (lane == 0) cpart[w] = acc;
    __syncthreads();
    if (threadIdx.x == 0) {
        float s = 0.0f;
#pragma unroll
        for (int i = 0; i < WPB; ++i) s += cpart[i];
        g_partials[b * NPART + blockIdx.x] = s;
        __threadfence();
        int d = atomicAdd(&g_done, 1);
        lastflag = (d == NCTAS - 1) ? 1 : 0;
    }
    __syncthreads();

    // Last CTA: deterministic fixed-order reduction of all partials.
    if (lastflag) {
        __threadfence();
        float s2 = 0.0f;
#pragma unroll
        for (int i = 0; i < NCTAS / TPB_MAIN; ++i)
            s2 += g_partials[threadIdx.x + i * TPB_MAIN];
#pragma unroll
        for (int o = 16; o > 0; o >>= 1)
            s2 += __shfl_xor_sync(0xFFFFFFFFu, s2, o);
        if (lane == 0) cpart[w] = s2;
        __syncthreads();
        if (threadIdx.x == 0) {
            float s3 = 0.0f;
#pragma unroll
            for (int i = 0; i < WPB; ++i) s3 += cpart[i];
            out[0] = s3 * (1.0f / (float)((size_t)BB * NN * KK));
            g_done = 0;  // reset for next graph replay
        }
    }
}

extern "C" void kernel_launch(void* const* d_in, const int* in_sizes, int n_in,
                              void* d_out, int out_size) {
    const float* pc = (const float*)d_in[0];
    const float* flow = (const float*)d_in[1];

    grid_build_kernel<<<BB, 1024>>>(pc);
    dim3 grid(NN / WPB, BB);
    knn_loss_kernel<<<grid, TPB_MAIN>>>(flow, (float*)d_out);
}

// round 7
// speedup vs baseline: 9.1851x; 1.1759x over previous
#include <cuda_runtime.h>

// KnnLoss via spatial grid, warp-per-query:
// B=4, N=8192, C=3, K=16, RADIUS=0.5, L2.
// Out-of-radius neighbors are replaced by self (zero contribution) => only
// the <=16 nearest in-radius neighbors matter. 16^3 grid (cell=0.5, clamped,
// monotone => in-radius pairs within +/-1 cell).
// Kernel 1 (4 CTAs): histogram (smem) + scan (smem, in-place) + scatter.
// Kernel 2: per query-warp: coalesced sweep (unpredicated loads over a
//   +32-padded array) with geometric row/corner trim, ballot-compaction of
//   packed keys (17-bit quantized d2 | 13-bit idx => unique, tie = lower idx
//   like top_k), register-resident tournament (REDUX.MIN over sorted 4-deep
//   or 8-deep per-lane lists; smem fallback for cnt>256, ~1% of queries);
//   parallel flow norms; last CTA reduces partials.

#define BB 4
#define NN 8192
#define KK 16
#define GRID 16
#define NCELLS (GRID * GRID * GRID)  // 4096
#define TPB_MAIN 256
#define WPB (TPB_MAIN / 32)          // 8 queries per CTA
#define CAP 512
#define NPART (NN / WPB)             // 1024 CTAs per batch
#define NCTAS (BB * NPART)           // 4096
#define IMAX 0x7FFFFFFF
#define RGATE 0.2500001f             // keep d2 whose sqrt rounds to <= 0.5
#define GATE2 0.2500002f             // prune bound (extra fp slack)

__device__ int g_offsets[BB * (NCELLS + 1)];
__device__ float4 g_sorted[BB * NN + 32];  // +32 pad: unpredicated sweep loads
__device__ float g_partials[NCTAS];
__device__ int g_done;  // zero-init; reset by last CTA each run

__device__ __forceinline__ int cell_coord(float v) {
    int c = (int)floorf((v + 4.0f) * 2.0f);
    return min(max(c, 0), GRID - 1);
}

#define CSWAP(a, b) { int t_ = min(a, b); b = max(a, b); a = t_; }

// ---- 1. fused grid build: histogram + scan + scatter (one CTA per batch) ---
#define PPT (NN / 1024)  // 8 points per thread
__global__ __launch_bounds__(1024) void grid_build_kernel(
    const float* __restrict__ pc) {
    __shared__ int hist[NCELLS];  // counts -> (in-place) exclusive offsets
    __shared__ int wtot[32];
    const int b = blockIdx.x, t = threadIdx.x;
    const int lane = t & 31, w = t >> 5;

#pragma unroll
    for (int i = 0; i < NCELLS / 1024; ++i) hist[t + i * 1024] = 0;
    __syncthreads();

    const float* pcb = pc + (size_t)b * NN * 3;
    float px[PPT], py[PPT], pz[PPT];
    int cell[PPT], rank[PPT];
#pragma unroll
    for (int i = 0; i < PPT; ++i) {
        int n = t + i * 1024;
        px[i] = pcb[3 * n + 0];
        py[i] = pcb[3 * n + 1];
        pz[i] = pcb[3 * n + 2];
        cell[i] = (cell_coord(pz[i]) * GRID + cell_coord(py[i])) * GRID +
                  cell_coord(px[i]);
        rank[i] = atomicAdd(&hist[cell[i]], 1);
    }
    __syncthreads();

    // Exclusive scan of hist (4 items/thread, shfl two-level), in place.
    int local[4];
    int run = 0;
#pragma unroll
    for (int i = 0; i < 4; ++i) {
        local[i] = run;
        run += hist[t * 4 + i];
    }
    int v = run;
#pragma unroll
    for (int o = 1; o < 32; o <<= 1) {
        int u = __shfl_up_sync(0xFFFFFFFFu, v, o);
        if (lane >= o) v += u;
    }
    if (lane == 31) wtot[w] = v;
    __syncthreads();
    if (w == 0) {
        int x = wtot[lane];
#pragma unroll
        for (int o = 1; o < 32; o <<= 1) {
            int u = __shfl_up_sync(0xFFFFFFFFu, x, o);
            if (lane >= o) x += u;
        }
        wtot[lane] = x;
    }
    __syncthreads();
    int excl = v - run + (w > 0 ? wtot[w - 1] : 0);
    int* gob = g_offsets + b * (NCELLS + 1);
#pragma unroll
    for (int i = 0; i < 4; ++i) {
        int o2 = excl + local[i];
        hist[t * 4 + i] = o2;
        gob[t * 4 + i] = o2;
    }
    if (t == 1023) gob[NCELLS] = excl + run;  // = NN
    __syncthreads();

    // Scatter from registers.
    float4* sbb = g_sorted + b * NN;
#pragma unroll
    for (int i = 0; i < PPT; ++i) {
        int pos = hist[cell[i]] + rank[i];
        sbb[pos] = make_float4(px[i], py[i], pz[i],
                               __int_as_float(t + i * 1024));
    }
}

// ---- 2. main: warp per query; last CTA finalizes ----
__global__ __launch_bounds__(TPB_MAIN) void knn_loss_kernel(
    const float* __restrict__ flow, float* __restrict__ out) {
    __shared__ int buf[WPB][CAP];
    __shared__ float cpart[WPB];
    __shared__ int lastflag;

    const int b = blockIdx.y;
    const int w = threadIdx.x >> 5;
    const int lane = threadIdx.x & 31;
    const unsigned lt_mask = (1u << lane) - 1u;
    const int sp = blockIdx.x * WPB + w;
    int* __restrict__ bw = buf[w];
    const float4* __restrict__ sb = g_sorted + b * NN;
    const int* __restrict__ ob = g_offsets + b * (NCELLS + 1);
    const float* __restrict__ flb = flow + (size_t)b * NN * 3;

    const float4 me = sb[sp];  // broadcast
    const int qi = __float_as_int(me.w);
    const int cx = cell_coord(me.x), cy = cell_coord(me.y),
              cz = cell_coord(me.z);

    // Per-axis band distances^2 (true lower bounds on d2 toward +/-1 cells).
    const float fx = fmaf((float)cx, -0.5f, me.x + 4.0f);
    const float fy = fmaf((float)cy, -0.5f, me.y + 4.0f);
    const float fz = fmaf((float)cz, -0.5f, me.z + 4.0f);
    const float fx2lo = fx * fx, fx2hi = (0.5f - fx) * (0.5f - fx);
    float dy2m[3], dz2m[3];
    dy2m[0] = fy * fy; dy2m[1] = 0.0f; dy2m[2] = (0.5f - fy) * (0.5f - fy);
    dz2m[0] = fz * fz; dz2m[1] = 0.0f; dz2m[2] = (0.5f - fz) * (0.5f - fz);

    // Phase 1: sweep + ballot compaction. Loads are unpredicated (array is
    // padded); validity folds into the in-radius predicate.
    int cnt = 0;  // warp-uniform
    const int x0 = max(cx - 1, 0);
    const int x1 = min(cx + 1, GRID - 1);
#pragma unroll
    for (int dz = -1; dz <= 1; ++dz) {
        int z2 = cz + dz;
        if ((unsigned)z2 >= (unsigned)GRID) continue;
#pragma unroll
        for (int dy = -1; dy <= 1; ++dy) {
            int y2 = cy + dy;
            if ((unsigned)y2 >= (unsigned)GRID) continue;
            float rd2 = dz2m[dz + 1] + dy2m[dy + 1];
            if (rd2 > GATE2) continue;  // whole row unreachable
            int xl = (rd2 + fx2lo > GATE2) ? cx : x0;
            int xh = (rd2 + fx2hi > GATE2) ? cx : x1;
            int base = (z2 * GRID + y2) * GRID;
            int s0 = ob[base + xl];
            int e0 = ob[base + xh + 1];
            for (int kb = s0; kb < e0; kb += 32) {
                int k = kb + lane;
                float4 p = sb[k];  // may read pad/garbage; gated below
                float ddx = me.x - p.x;
                float ddy = me.y - p.y;
                float ddz = me.z - p.z;
                float d2 = fmaf(ddx, ddx, fmaf(ddy, ddy, ddz * ddz));
                bool inr = (d2 < RGATE) & (k < e0);
                unsigned mask = __ballot_sync(0xFFFFFFFFu, inr);
                if (inr) {
                    int key = ((int)(d2 * 262144.0f) << 13) |
                              __float_as_int(p.w);
                    int pos = cnt + __popc(mask & lt_mask);
                    if (pos < CAP) bw[pos] = key;
                }
                cnt += __popc(mask);
            }
        }
    }
    cnt = min(cnt, CAP);
    __syncwarp();

    // Phase 2: top-16 selection; round r's winner parks on lane r.
    const int R = min(cnt, KK);
    int selkey = IMAX;
    if (cnt <= 128) {
        // 4-deep register tournament.
        int v0 = (lane < cnt) ? bw[lane] : IMAX;
        int v1 = (lane + 32 < cnt) ? bw[lane + 32] : IMAX;
        int v2 = (lane + 64 < cnt) ? bw[lane + 64] : IMAX;
        int v3 = (lane + 96 < cnt) ? bw[lane + 96] : IMAX;
        CSWAP(v0, v1); CSWAP(v2, v3); CSWAP(v0, v2); CSWAP(v1, v3);
        CSWAP(v1, v2);
        for (int r = 0; r < R; ++r) {
            int gmin = __reduce_min_sync(0xFFFFFFFFu, v0);
            bool won = (v0 == gmin);  // keys unique => exactly one winner
            v0 = won ? v1 : v0;
            v1 = won ? v2 : v1;
            v2 = won ? v3 : v2;
            v3 = won ? IMAX : v3;
            if (lane == r) selkey = gmin;
        }
    } else if (cnt <= 256) {
        // 8-deep register tournament (covers all but ~1% of queries).
        int v0 = (lane < cnt) ? bw[lane] : IMAX;
        int v1 = (lane + 32 < cnt) ? bw[lane + 32] : IMAX;
        int v2 = (lane + 64 < cnt) ? bw[lane + 64] : IMAX;
        int v3 = (lane + 96 < cnt) ? bw[lane + 96] : IMAX;
        int v4 = (lane + 128 < cnt) ? bw[lane + 128] : IMAX;
        int v5 = (lane + 160 < cnt) ? bw[lane + 160] : IMAX;
        int v6 = (lane + 192 < cnt) ? bw[lane + 192] : IMAX;
        int v7 = (lane + 224 < cnt) ? bw[lane + 224] : IMAX;
        // Batcher odd-even merge sort for 8 (19 comparators).
        CSWAP(v0, v1); CSWAP(v2, v3); CSWAP(v4, v5); CSWAP(v6, v7);
        CSWAP(v0, v2); CSWAP(v1, v3); CSWAP(v4, v6); CSWAP(v5, v7);
        CSWAP(v1, v2); CSWAP(v5, v6);
        CSWAP(v0, v4); CSWAP(v1, v5); CSWAP(v2, v6); CSWAP(v3, v7);
        CSWAP(v2, v4); CSWAP(v3, v5);
        CSWAP(v1, v2); CSWAP(v3, v4); CSWAP(v5, v6);
        for (int r = 0; r < R; ++r) {
            int gmin = __reduce_min_sync(0xFFFFFFFFu, v0);
            bool won = (v0 == gmin);
            v0 = won ? v1 : v0;
            v1 = won ? v2 : v1;
            v2 = won ? v3 : v2;
            v3 = won ? v4 : v3;
            v4 = won ? v5 : v4;
            v5 = won ? v6 : v5;
            v6 = won ? v7 : v6;
            v7 = won ? IMAX : v7;
            if (lane == r) selkey = gmin;
        }
    } else {
        const int P = (cnt + 31) >> 5;
        for (int r = 0; r < R; ++r) {
            int mymin = IMAX, myidx = 0;
            for (int i = 0; i < P; ++i) {
                int k = lane + (i << 5);
                int vv = (k < cnt) ? bw[k] : IMAX;
                if (vv < mymin) { mymin = vv; myidx = k; }
            }
            int gmin = __reduce_min_sync(0xFFFFFFFFu, mymin);
            if (mymin == gmin && gmin != IMAX) bw[myidx] = IMAX;
            if (lane == r) selkey = gmin;
            __syncwarp();
        }
    }

    // Phase 3: lanes 0..R-1 hold selected keys; parallel norms + reduce.
    float acc = 0.0f;
    if (selkey != IMAX) {
        const int j = selkey & (NN - 1);  // j==qi (self) => exact 0
        float ddx = flb[3 * qi + 0] - flb[3 * j + 0];
        float ddy = flb[3 * qi + 1] - flb[3 * j + 1];
        float ddz = flb[3 * qi + 2] - flb[3 * j + 2];
        acc = __fsqrt_rn(fmaf(ddx, ddx, fmaf(ddy, ddy, ddz * ddz)));
    }
#pragma unroll
    for (int o = 16; o > 0; o >>= 1)
        acc += __shfl_xor_sync(0xFFFFFFFFu, acc, o);
    if (lane == 0) cpart[w] = acc;
    __syncthreads();
    if (threadIdx.x == 0) {
        float s = 0.0f;
#pragma unroll
        for (int i = 0; i < WPB; ++i) s += cpart[i];
        g_partials[b * NPART + blockIdx.x] = s;
        __threadfence();
        int d = atomicAdd(&g_done, 1);
        lastflag = (d == NCTAS - 1) ? 1 : 0;
    }
    __syncthreads();

    // Last CTA: deterministic fixed-order reduction of all partials.
    if (lastflag) {
        __threadfence();
        float s2 = 0.0f;
#pragma unroll
        for (int i = 0; i < NCTAS / TPB_MAIN; ++i)
            s2 += g_partials[threadIdx.x + i * TPB_MAIN];
#pragma unroll
        for (int o = 16; o > 0; o >>= 1)
            s2 += __shfl_xor_sync(0xFFFFFFFFu, s2, o);
        if (lane == 0) cpart[w] = s2;
        __syncthreads();
        if (threadIdx.x == 0) {
            float s3 = 0.0f;
#pragma unroll
            for (int i = 0; i < WPB; ++i) s3 += cpart[i];
            out[0] = s3 * (1.0f / (float)((size_t)BB * NN * KK));
            g_done = 0;  // reset for next graph replay
        }
    }
}

extern "C" void kernel_launch(void* const* d_in, const int* in_sizes, int n_in,
                              void* d_out, int out_size) {
    const float* pc = (const float*)d_in[0];
    const float* flow = (const float*)d_in[1];

    grid_build_kernel<<<BB, 1024>>>(pc);
    dim3 grid(NN / WPB, BB);
    knn_loss_kernel<<<grid, TPB_MAIN>>>(flow, (float*)d_out);
}